// round 2
// baseline (speedup 1.0000x reference)
#include <cuda_runtime.h>

typedef unsigned long long ull;

// ---------- packed f32x2 helpers (Blackwell FFMA2 path) ----------
__device__ __forceinline__ ull pack2_dup(float x) {
    ull r; asm("mov.b64 %0, {%1, %1};" : "=l"(r) : "f"(x)); return r;
}
__device__ __forceinline__ ull ffma2(ull a, ull b, ull c) {
    ull d; asm("fma.rn.f32x2 %0, %1, %2, %3;" : "=l"(d) : "l"(a), "l"(b), "l"(c)); return d;
}
__device__ __forceinline__ float2 unpack2(ull v) {
    float x, y; asm("mov.b64 {%0, %1}, %2;" : "=f"(x), "=f"(y) : "l"(v));
    float2 f; f.x = x; f.y = y; return f;
}

#define S_LEN 2048
#define B_SZ  64
#define D_SZ  512
#define H_SZ  512
#define M_TOT (B_SZ * S_LEN)   // 131072

// ---------- static device scratch (no allocations allowed) ----------
__device__ float    g_proj[(size_t)M_TOT * H_SZ];   // 268 MB
__device__ float    g_pin [(size_t)M_TOT * H_SZ];   // 268 MB, layout [s][b][g]
__device__ float    g_h   [2][B_SZ * H_SZ];         // double-buffered recurrent state
__device__ unsigned g_cnt [S_LEN * 16];             // per-step per-batch-group arrival counters

// =====================================================================
// Init: zero the per-step barrier counters (fresh every run / replay)
// =====================================================================
__global__ void init_kernel() {
    int i = blockIdx.x * blockDim.x + threadIdx.x;
    if (i < S_LEN * 16) g_cnt[i] = 0u;
}

// =====================================================================
// GEMM: C[m,n] = act( sum_k A[m,k] * W[n,k] + bias[n] )
//   MODE 0: A = Ain (X), tanh, write g_proj[m*512+n]
//   MODE 1: A = g_proj,  no act, write g_pin[s*32768 + b*512 + n]  (m = b*2048+s)
// BM=BN=128, BK=16, 256 threads, 8x8 micro-tile, packed f32x2 FMA.
// =====================================================================
template<int MODE>
__global__ void __launch_bounds__(256, 2)
gemm_kernel(const float* __restrict__ Ain, const float* __restrict__ W,
            const float* __restrict__ bias, int ldw)
{
    __shared__ float As[16][128];
    __shared__ float Bs[16][128];

    const float* A = (MODE == 0) ? Ain : g_proj;

    const int t  = threadIdx.x;
    const int n0 = blockIdx.x * 128;
    const int m0 = blockIdx.y * 128;
    const int tx = t & 15;        // 0..15 -> n micro
    const int ty = t >> 4;        // 0..15 -> m micro
    const int lrow = t >> 2;      // 0..63
    const int lc4  = (t & 3) * 4; // 0,4,8,12

    ull acc[8][4];
    #pragma unroll
    for (int i = 0; i < 8; i++)
        #pragma unroll
        for (int j = 0; j < 4; j++) acc[i][j] = 0ull;

    for (int k0 = 0; k0 < D_SZ; k0 += 16) {
        float4 av0 = *(const float4*)&A[(size_t)(m0 + lrow)      * D_SZ + k0 + lc4];
        float4 av1 = *(const float4*)&A[(size_t)(m0 + lrow + 64) * D_SZ + k0 + lc4];
        float4 bv0 = *(const float4*)&W[(size_t)(n0 + lrow)      * ldw + k0 + lc4];
        float4 bv1 = *(const float4*)&W[(size_t)(n0 + lrow + 64) * ldw + k0 + lc4];

        __syncthreads();
        As[lc4 + 0][lrow] = av0.x; As[lc4 + 1][lrow] = av0.y;
        As[lc4 + 2][lrow] = av0.z; As[lc4 + 3][lrow] = av0.w;
        As[lc4 + 0][lrow + 64] = av1.x; As[lc4 + 1][lrow + 64] = av1.y;
        As[lc4 + 2][lrow + 64] = av1.z; As[lc4 + 3][lrow + 64] = av1.w;
        Bs[lc4 + 0][lrow] = bv0.x; Bs[lc4 + 1][lrow] = bv0.y;
        Bs[lc4 + 2][lrow] = bv0.z; Bs[lc4 + 3][lrow] = bv0.w;
        Bs[lc4 + 0][lrow + 64] = bv1.x; Bs[lc4 + 1][lrow + 64] = bv1.y;
        Bs[lc4 + 2][lrow + 64] = bv1.z; Bs[lc4 + 3][lrow + 64] = bv1.w;
        __syncthreads();

        #pragma unroll
        for (int kk = 0; kk < 16; kk++) {
            ulonglong2 b01 = *(const ulonglong2*)&Bs[kk][tx * 8];
            ulonglong2 b23 = *(const ulonglong2*)&Bs[kk][tx * 8 + 4];
            float4 a03 = *(const float4*)&As[kk][ty * 8];
            float4 a47 = *(const float4*)&As[kk][ty * 8 + 4];
            float aa[8] = {a03.x, a03.y, a03.z, a03.w, a47.x, a47.y, a47.z, a47.w};
            #pragma unroll
            for (int i = 0; i < 8; i++) {
                ull ap = pack2_dup(aa[i]);
                acc[i][0] = ffma2(ap, b01.x, acc[i][0]);
                acc[i][1] = ffma2(ap, b01.y, acc[i][1]);
                acc[i][2] = ffma2(ap, b23.x, acc[i][2]);
                acc[i][3] = ffma2(ap, b23.y, acc[i][3]);
            }
        }
    }

    float bvals[8];
    #pragma unroll
    for (int j = 0; j < 8; j++) bvals[j] = bias[n0 + tx * 8 + j];

    #pragma unroll
    for (int i = 0; i < 8; i++) {
        const int m = m0 + ty * 8 + i;
        float v[8];
        #pragma unroll
        for (int jp = 0; jp < 4; jp++) {
            float2 p = unpack2(acc[i][jp]);
            v[2 * jp + 0] = p.x + bvals[2 * jp + 0];
            v[2 * jp + 1] = p.y + bvals[2 * jp + 1];
        }
        if (MODE == 0) {
            #pragma unroll
            for (int j = 0; j < 8; j++) v[j] = tanhf(v[j]);
            float* dst = &g_proj[(size_t)m * H_SZ + n0 + tx * 8];
            *(float4*)(dst + 0) = make_float4(v[0], v[1], v[2], v[3]);
            *(float4*)(dst + 4) = make_float4(v[4], v[5], v[6], v[7]);
        } else {
            const int ss = m & (S_LEN - 1);
            const int bb = m >> 11;
            float* dst = &g_pin[(size_t)ss * (B_SZ * H_SZ) + (size_t)bb * H_SZ + n0 + tx * 8];
            *(float4*)(dst + 0) = make_float4(v[0], v[1], v[2], v[3]);
            *(float4*)(dst + 4) = make_float4(v[4], v[5], v[6], v[7]);
        }
    }
}

// =====================================================================
// Scan: 2048 sequential steps  h = tanh(pin[s] + h @ Wr2^T)
// Grid: 128 CTAs = 16 batch-groups (4 batches) x 8 col-groups (64 cols).
// Wr2 slice register-resident per thread (128 floats, loaded once).
// Per-batch-group barrier via per-step atomic counters (8 CTAs/group).
// =====================================================================
__global__ void __launch_bounds__(256, 1)
scan_kernel(const float* __restrict__ Wr, float* __restrict__ out)
{
    __shared__ float h_s[H_SZ * 4];    // [k][b], 8 KB
    __shared__ float red[4 * 64 * 4];  // [qk][c][b], 4 KB

    const int t  = threadIdx.x;
    const int q  = blockIdx.x & 7;     // col group (64 cols)
    const int g  = blockIdx.x >> 3;    // batch group (4 batches)
    const int c  = t & 63;             // col within group (dot phase)
    const int qk = t >> 6;             // k-quarter (dot phase)
    const int cb = t & 63;             // col (reduce phase)
    const int bb = t >> 6;             // batch-in-group (reduce phase)
    const int b_glob = g * 4 + bb;

    // ---- register-resident Wr2 slice: row (q*64+c), k in [qk*128, qk*128+128) ----
    const float* wrow = Wr + (size_t)(q * 64 + c) * 1024 + 512 + qk * 128;
    float w[128];
    #pragma unroll
    for (int i = 0; i < 32; i++) {
        float4 v = *(const float4*)&wrow[i * 4];
        w[4 * i + 0] = v.x; w[4 * i + 1] = v.y; w[4 * i + 2] = v.z; w[4 * i + 3] = v.w;
    }

    const float* hq_base;  // set per step
    volatile unsigned* vcnt = g_cnt;

    for (int s = 0; s < S_LEN; s++) {
        // prefetch this step's pin element (independent of barrier)
        const float p_val =
            __ldg(&g_pin[(size_t)s * (B_SZ * H_SZ) + (size_t)b_glob * H_SZ + q * 64 + cb]);

        // wait for previous step's producers (own batch group only)
        if (s > 0) {
            if (t == 0) {
                while (vcnt[(s - 1) * 16 + g] < 8u) { __nanosleep(32); }
                __threadfence();
            }
        }
        __syncthreads();

        // stage h into smem as [k][b] (skip step 0: h == 0)
        if (s > 0) {
            const int p = s & 1;
            const float* hsrc = &g_h[p][g * 4 * H_SZ];
            #pragma unroll
            for (int j = 0; j < 8; j++) {
                int idx = t + j * 256;
                int b = idx >> 9;
                int k = idx & 511;
                h_s[k * 4 + b] = hsrc[b * H_SZ + k];
            }
        }
        __syncthreads();

        // quarter-dot: acc over k in [qk*128, qk*128+128), 4 batches packed f32x2
        ull acc01 = 0ull, acc23 = 0ull;
        if (s > 0) {
            hq_base = &h_s[qk * 128 * 4];
            #pragma unroll
            for (int kk = 0; kk < 128; kk++) {
                ulonglong2 hv = *(const ulonglong2*)&hq_base[kk * 4];
                ull wp = pack2_dup(w[kk]);
                acc01 = ffma2(hv.x, wp, acc01);
                acc23 = ffma2(hv.y, wp, acc23);
            }
        }
        *(ull*)&red[qk * 256 + c * 4 + 0] = acc01;
        *(ull*)&red[qk * 256 + c * 4 + 2] = acc23;
        __syncthreads();

        // reduce quarters + bias-in (pin) + tanh
        float sum = red[0 * 256 + cb * 4 + bb] + red[1 * 256 + cb * 4 + bb] +
                    red[2 * 256 + cb * 4 + bb] + red[3 * 256 + cb * 4 + bb];
        float val = tanhf(sum + p_val);

        // publish new state + output (out is [b][s][h])
        g_h[(s + 1) & 1][b_glob * H_SZ + q * 64 + cb] = val;
        out[(size_t)b_glob * (S_LEN * H_SZ) + (size_t)s * H_SZ + q * 64 + cb] = val;

        __syncthreads();
        if (t == 0) {
            __threadfence();
            atomicAdd(&g_cnt[s * 16 + g], 1u);
        }
    }
}

// =====================================================================
extern "C" void kernel_launch(void* const* d_in, const int* in_sizes, int n_in,
                              void* d_out, int out_size)
{
    const float* X  = (const float*)d_in[0];
    const float* Wp = (const float*)d_in[1];
    const float* bp = (const float*)d_in[2];
    const float* Wr = (const float*)d_in[3];
    const float* br = (const float*)d_in[4];
    float* out = (float*)d_out;

    init_kernel<<<128, 256>>>();
    gemm_kernel<0><<<dim3(4, 1024), 256>>>(X, Wp, bp, 512);
    gemm_kernel<1><<<dim3(4, 1024), 256>>>(nullptr, Wr, br, 1024);
    scan_kernel<<<128, 256>>>(Wr, out);
}